// round 2
// baseline (speedup 1.0000x reference)
#include <cuda_runtime.h>

#define Bsz 16384
#define Cn  8
#define Dd  256
#define H0n 512
#define H1n 256

#define TM       64
#define NTHREADS 256

// shared memory layout (float offsets)
#define XS_PITCH  68            // x transposed [Dd][68]
#define XS_OFF    0
#define H0S_PITCH 516           // h0 row-major [64][516]
#define H0S_OFF   (Dd * XS_PITCH)                    // 17408
#define WT_PITCH  260           // W tile transposed [16][260]
#define WT_OFF    (H0S_OFF + TM * H0S_PITCH)         // 50432
#define B0S_OFF   (WT_OFF + 16 * WT_PITCH)           // 54592
#define B1S_OFF   (B0S_OFF + H0n)                    // 55104
#define W2S_OFF   (B1S_OFF + H1n)                    // 55360
#define OUTS_OFF  (W2S_OFF + H1n)                    // 55616
#define SMEM_FLOATS (OUTS_OFF + TM)                  // 55680 -> 222720 B

typedef unsigned long long u64;

__device__ __forceinline__ u64 pack2(float lo, float hi) {
    u64 r; asm("mov.b64 %0, {%1, %2};" : "=l"(r) : "f"(lo), "f"(hi)); return r;
}
__device__ __forceinline__ void unpack2(u64 v, float &lo, float &hi) {
    asm("mov.b64 {%0, %1}, %2;" : "=f"(lo), "=f"(hi) : "l"(v));
}
// packed dual FMA: d.lo += a.lo*b.lo ; d.hi += a.hi*b.hi
__device__ __forceinline__ void ffma2(u64 &d, u64 a, u64 b) {
    asm("fma.rn.f32x2 %0, %1, %2, %0;" : "+l"(d) : "l"(a), "l"(b));
}

// ---- W tile load (global -> regs) and store (regs -> smem transposed) ----
#define LOADW(Wc, Kdim, nbase, kbase) do {                                   \
    const float* _p = (Wc) + (size_t)((nbase) + nl) * (Kdim) + (kbase) + kq * 4; \
    p0 = *(const float4*)(_p);                                               \
    p1 = *(const float4*)(_p + (size_t)64  * (Kdim));                        \
    p2 = *(const float4*)(_p + (size_t)128 * (Kdim));                        \
    p3 = *(const float4*)(_p + (size_t)192 * (Kdim));                        \
} while (0)

#define STSW() do {                                                          \
    float* _w = wt + (kq * 4) * WT_PITCH + nl;                               \
    _w[0*WT_PITCH +   0] = p0.x; _w[1*WT_PITCH +   0] = p0.y;                \
    _w[2*WT_PITCH +   0] = p0.z; _w[3*WT_PITCH +   0] = p0.w;                \
    _w[0*WT_PITCH +  64] = p1.x; _w[1*WT_PITCH +  64] = p1.y;                \
    _w[2*WT_PITCH +  64] = p1.z; _w[3*WT_PITCH +  64] = p1.w;                \
    _w[0*WT_PITCH + 128] = p2.x; _w[1*WT_PITCH + 128] = p2.y;                \
    _w[2*WT_PITCH + 128] = p2.z; _w[3*WT_PITCH + 128] = p2.w;                \
    _w[0*WT_PITCH + 192] = p3.x; _w[1*WT_PITCH + 192] = p3.y;                \
    _w[2*WT_PITCH + 192] = p3.z; _w[3*WT_PITCH + 192] = p3.w;                \
} while (0)

// one k-slice of the 4x16 microtile given packed a0..a3
#define MICRO_FMA(k2)                                                        \
    _Pragma("unroll")                                                        \
    for (int cc = 0; cc < 4; cc++) {                                         \
        const float4 bv = *(const float4*)(wt + (k2) * WT_PITCH + cc * 64 + tx * 4); \
        u64 bA = pack2(bv.x, bv.y);                                          \
        u64 bB = pack2(bv.z, bv.w);                                          \
        ffma2(acc[0*8 + cc*2 + 0], a0, bA); ffma2(acc[0*8 + cc*2 + 1], a0, bB); \
        ffma2(acc[1*8 + cc*2 + 0], a1, bA); ffma2(acc[1*8 + cc*2 + 1], a1, bB); \
        ffma2(acc[2*8 + cc*2 + 0], a2, bA); ffma2(acc[2*8 + cc*2 + 1], a2, bB); \
        ffma2(acc[3*8 + cc*2 + 0], a3, bA); ffma2(acc[3*8 + cc*2 + 1], a3, bB); \
    }

__global__ void __launch_bounds__(NTHREADS, 1)
confounder_fused_kernel(const float* __restrict__ x,
                        const float* __restrict__ W0,
                        const float* __restrict__ b0,
                        const float* __restrict__ W1,
                        const float* __restrict__ b1,
                        const float* __restrict__ W2,
                        const float* __restrict__ b2,
                        float* __restrict__ out)
{
    extern __shared__ float sm[];
    const int tid  = threadIdx.x;
    const int tx   = tid & 15;
    const int ty   = tid >> 4;
    const int row0 = blockIdx.x * TM;
    const int c    = blockIdx.y;

    const int kq = tid & 3;     // k quad within 16-k tile
    const int nl = tid >> 2;    // n lane 0..63

    float* xs   = sm + XS_OFF;
    float* h0s  = sm + H0S_OFF;
    float* wt   = sm + WT_OFF;
    float* b0s  = sm + B0S_OFF;
    float* b1s  = sm + B1S_OFF;
    float* w2s  = sm + W2S_OFF;
    float* outs = sm + OUTS_OFF;

    // ---- preamble: biases, w2, zero out accumulator, x tile (transposed) ----
    for (int i = tid; i < H0n; i += NTHREADS) b0s[i] = b0[c * H0n + i];
    for (int i = tid; i < H1n; i += NTHREADS) b1s[i] = b1[c * H1n + i];
    for (int i = tid; i < H1n; i += NTHREADS) w2s[i] = W2[c * H1n + i];
    if (tid < TM) outs[tid] = 0.0f;

    {
        const int row = tid & 63;
        const int cg0 = tid >> 6;   // 0..3
        #pragma unroll
        for (int i = 0; i < 16; i++) {
            const int c4 = cg0 + i * 4;   // 0..63
            const float4 v = *(const float4*)(x + (size_t)(row0 + row) * Dd + c4 * 4);
            xs[(c4 * 4 + 0) * XS_PITCH + row] = v.x;
            xs[(c4 * 4 + 1) * XS_PITCH + row] = v.y;
            xs[(c4 * 4 + 2) * XS_PITCH + row] = v.z;
            xs[(c4 * 4 + 3) * XS_PITCH + row] = v.w;
        }
    }

    float4 p0, p1, p2, p3;

    // =================== Layer 0: h0 = relu(x @ W0[c]^T + b0) ===================
    {
        const float* Wc = W0 + (size_t)c * H0n * Dd;
        #pragma unroll 1
        for (int nn = 0; nn < 2; nn++) {
            const int nbase = nn * 256;
            u64 acc[32];
            #pragma unroll
            for (int q = 0; q < 32; q++) acc[q] = 0ULL;

            LOADW(Wc, Dd, nbase, 0);
            __syncthreads();            // wt free of previous readers; xs/bias visible
            STSW();
            __syncthreads();

            const int NK = Dd / 16;     // 16
            #pragma unroll 1
            for (int kk = 0; kk < NK; kk++) {
                if (kk + 1 < NK) LOADW(Wc, Dd, nbase, (kk + 1) * 16);
                const int kbase = kk * 16;
                #pragma unroll
                for (int k2 = 0; k2 < 16; k2++) {
                    const float4 av = *(const float4*)(xs + (kbase + k2) * XS_PITCH + ty * 4);
                    u64 a0 = pack2(av.x, av.x);
                    u64 a1 = pack2(av.y, av.y);
                    u64 a2 = pack2(av.z, av.z);
                    u64 a3 = pack2(av.w, av.w);
                    MICRO_FMA(k2)
                }
                if (kk + 1 < NK) { __syncthreads(); STSW(); __syncthreads(); }
            }

            // epilogue: bias + relu -> h0s (row-major)
            #pragma unroll
            for (int i = 0; i < 4; i++) {
                const int m = ty * 4 + i;
                #pragma unroll
                for (int cc = 0; cc < 4; cc++) {
                    float e0, e1, e2, e3;
                    unpack2(acc[i*8 + cc*2 + 0], e0, e1);
                    unpack2(acc[i*8 + cc*2 + 1], e2, e3);
                    const int n = nbase + cc * 64 + tx * 4;
                    float4 o;
                    o.x = fmaxf(e0 + b0s[n + 0], 0.0f);
                    o.y = fmaxf(e1 + b0s[n + 1], 0.0f);
                    o.z = fmaxf(e2 + b0s[n + 2], 0.0f);
                    o.w = fmaxf(e3 + b0s[n + 3], 0.0f);
                    *(float4*)(h0s + m * H0S_PITCH + n) = o;
                }
            }
        }
    }

    // =================== Layer 1 + head: out = relu(h0 @ W1^T + b1) . w2 + b2 ===================
    {
        const float* Wc = W1 + (size_t)c * H1n * H0n;
        u64 acc[32];
        #pragma unroll
        for (int q = 0; q < 32; q++) acc[q] = 0ULL;

        LOADW(Wc, H0n, 0, 0);
        __syncthreads();            // h0s complete + wt free
        STSW();
        __syncthreads();

        const int NK = H0n / 16;    // 32
        #pragma unroll 1
        for (int kk = 0; kk < NK; kk++) {
            if (kk + 1 < NK) LOADW(Wc, H0n, 0, (kk + 1) * 16);
            const int kbase = kk * 16;
            #pragma unroll
            for (int k2 = 0; k2 < 16; k2++) {
                const int kg = kbase + k2;
                const float v0 = h0s[(ty * 4 + 0) * H0S_PITCH + kg];
                const float v1 = h0s[(ty * 4 + 1) * H0S_PITCH + kg];
                const float v2 = h0s[(ty * 4 + 2) * H0S_PITCH + kg];
                const float v3 = h0s[(ty * 4 + 3) * H0S_PITCH + kg];
                u64 a0 = pack2(v0, v0);
                u64 a1 = pack2(v1, v1);
                u64 a2 = pack2(v2, v2);
                u64 a3 = pack2(v3, v3);
                MICRO_FMA(k2)
            }
            if (kk + 1 < NK) { __syncthreads(); STSW(); __syncthreads(); }
        }

        // epilogue: bias + relu, dot with w2, reduce into outs
        #pragma unroll
        for (int i = 0; i < 4; i++) {
            float s = 0.0f;
            #pragma unroll
            for (int cc = 0; cc < 4; cc++) {
                float e0, e1, e2, e3;
                unpack2(acc[i*8 + cc*2 + 0], e0, e1);
                unpack2(acc[i*8 + cc*2 + 1], e2, e3);
                const int n = cc * 64 + tx * 4;
                s += fmaxf(e0 + b1s[n + 0], 0.0f) * w2s[n + 0];
                s += fmaxf(e1 + b1s[n + 1], 0.0f) * w2s[n + 1];
                s += fmaxf(e2 + b1s[n + 2], 0.0f) * w2s[n + 2];
                s += fmaxf(e3 + b1s[n + 3], 0.0f) * w2s[n + 3];
            }
            atomicAdd(&outs[ty * 4 + i], s);
        }
    }

    __syncthreads();
    if (tid < TM) {
        out[(size_t)(row0 + tid) * Cn + c] = outs[tid] + b2[c];
    }
}

extern "C" void kernel_launch(void* const* d_in, const int* in_sizes, int n_in,
                              void* d_out, int out_size) {
    (void)in_sizes; (void)n_in; (void)out_size;
    const float* x  = (const float*)d_in[0];
    const float* W0 = (const float*)d_in[1];
    const float* b0 = (const float*)d_in[2];
    const float* W1 = (const float*)d_in[3];
    const float* b1 = (const float*)d_in[4];
    const float* W2 = (const float*)d_in[5];
    const float* b2 = (const float*)d_in[6];
    float* out = (float*)d_out;

    cudaFuncSetAttribute(confounder_fused_kernel,
                         cudaFuncAttributeMaxDynamicSharedMemorySize,
                         SMEM_FLOATS * sizeof(float));

    dim3 grid(Bsz / TM, Cn);
    confounder_fused_kernel<<<grid, NTHREADS, SMEM_FLOATS * sizeof(float)>>>(
        x, W0, b0, W1, b1, W2, b2, out);
}

// round 4
// speedup vs baseline: 2.1853x; 2.1853x over previous
#include <cuda_runtime.h>
#include <cuda_bf16.h>
#include <cstdint>

#define Bsz 16384
#define Cn  8
#define Dd  256
#define H0n 512
#define H1n 256

// ---------------- scratch (device statics; no runtime alloc) ----------------
__device__ __align__(16) __nv_bfloat16 g_xbig [Bsz][768];         // 25MB  [x_hi | x_lo | x_hi]
__device__ __align__(16) __nv_bfloat16 g_w0big[Cn][H0n][768];     // 6.3MB [w_hi | w_hi | w_lo]
__device__ __align__(16) __nv_bfloat16 g_w1big[Cn][H1n][1536];    // 6.3MB [w_hi | w_hi | w_lo]
__device__ __align__(16) __nv_bfloat16 g_h0   [Cn][Bsz][1024];    // 268MB [h_hi | h_lo]

// ---------------- helpers ----------------
__device__ __forceinline__ void split8(const float* s, uint4& hi, uint4& lo) {
    uint32_t h[4], l[4];
    #pragma unroll
    for (int i = 0; i < 4; i++) {
        float v0 = s[2*i], v1 = s[2*i+1];
        __nv_bfloat16 h0 = __float2bfloat16(v0), h1 = __float2bfloat16(v1);
        __nv_bfloat16 l0 = __float2bfloat16(v0 - __bfloat162float(h0));
        __nv_bfloat16 l1 = __float2bfloat16(v1 - __bfloat162float(h1));
        h[i] = (uint32_t)__bfloat16_as_ushort(h0) | ((uint32_t)__bfloat16_as_ushort(h1) << 16);
        l[i] = (uint32_t)__bfloat16_as_ushort(l0) | ((uint32_t)__bfloat16_as_ushort(l1) << 16);
    }
    hi = make_uint4(h[0], h[1], h[2], h[3]);
    lo = make_uint4(l[0], l[1], l[2], l[3]);
}

__global__ void prep_x(const float* __restrict__ x) {
    int u = blockIdx.x * blockDim.x + threadIdx.x;   // 524288
    int k8 = u & 31, b = u >> 5;
    float buf[8];
    *(float4*)(buf)   = *(const float4*)(x + (size_t)b * Dd + k8 * 8);
    *(float4*)(buf+4) = *(const float4*)(x + (size_t)b * Dd + k8 * 8 + 4);
    uint4 hi, lo; split8(buf, hi, lo);
    *(uint4*)&g_xbig[b][k8 * 8]       = hi;
    *(uint4*)&g_xbig[b][256 + k8 * 8] = lo;
    *(uint4*)&g_xbig[b][512 + k8 * 8] = hi;
}
__global__ void prep_w0(const float* __restrict__ W0) {
    int u = blockIdx.x * blockDim.x + threadIdx.x;   // 131072
    int k8 = u & 31, n = (u >> 5) & 511, c = u >> 14;
    float buf[8];
    const float* src = W0 + ((size_t)c * H0n + n) * Dd + k8 * 8;
    *(float4*)(buf)   = *(const float4*)(src);
    *(float4*)(buf+4) = *(const float4*)(src + 4);
    uint4 hi, lo; split8(buf, hi, lo);
    *(uint4*)&g_w0big[c][n][k8 * 8]       = hi;
    *(uint4*)&g_w0big[c][n][256 + k8 * 8] = hi;
    *(uint4*)&g_w0big[c][n][512 + k8 * 8] = lo;
}
__global__ void prep_w1(const float* __restrict__ W1) {
    int u = blockIdx.x * blockDim.x + threadIdx.x;   // 131072
    int k8 = u & 63, n = (u >> 6) & 255, c = u >> 14;
    float buf[8];
    const float* src = W1 + ((size_t)c * H1n + n) * H0n + k8 * 8;
    *(float4*)(buf)   = *(const float4*)(src);
    *(float4*)(buf+4) = *(const float4*)(src + 4);
    uint4 hi, lo; split8(buf, hi, lo);
    *(uint4*)&g_w1big[c][n][k8 * 8]        = hi;
    *(uint4*)&g_w1big[c][n][512 + k8 * 8]  = hi;
    *(uint4*)&g_w1big[c][n][1024 + k8 * 8] = lo;
}

// ---------------- GEMM machinery ----------------
__device__ __forceinline__ uint32_t smem_u32(const void* p) {
    uint32_t a;
    asm("{ .reg .u64 t; cvta.to.shared.u64 t, %1; cvt.u32.u64 %0, t; }" : "=r"(a) : "l"(p));
    return a;
}
#define CP16(dst, src) asm volatile("cp.async.cg.shared.global [%0], [%1], 16;" :: "r"(dst), "l"(src))
#define CP_COMMIT()    asm volatile("cp.async.commit_group;" ::: "memory")
#define CP_WAIT1()     asm volatile("cp.async.wait_group 1;" ::: "memory")
#define LDSM4(r, a) \
    asm volatile("ldmatrix.sync.aligned.m8n8.x4.shared.b16 {%0,%1,%2,%3}, [%4];" \
        : "=r"((r)[0]), "=r"((r)[1]), "=r"((r)[2]), "=r"((r)[3]) : "r"(a))
#define MMA(d, a, b0, b1) \
    asm volatile("mma.sync.aligned.m16n8k16.row.col.f32.bf16.bf16.f32 " \
        "{%0,%1,%2,%3}, {%4,%5,%6,%7}, {%8,%9}, {%0,%1,%2,%3};" \
        : "+f"((d)[0]), "+f"((d)[1]), "+f"((d)[2]), "+f"((d)[3]) \
        : "r"((a)[0]), "r"((a)[1]), "r"((a)[2]), "r"((a)[3]), "r"(b0), "r"(b1))

// stage: A[128][64] (16KB) + B[256][64] (32KB) = 48KB, 3 stages
#define STAGE_BYTES 49152
#define AUX_OFF     147456
#define SMEM_TOTAL  151552

// one k16 compute step over a 64x64 warp tile against 256-wide B (4 n16 groups of this warp)
#define COMPUTE_K16(s16) do {                                                  \
    uint32_t afr[4][4], bfr[4][4];                                             \
    _Pragma("unroll")                                                          \
    for (int mt = 0; mt < 4; mt++) {                                           \
        int row = wm0 + mt * 16 + (lane & 7) + ((lane >> 3) & 1) * 8;          \
        int g   = (s16) * 2 + (lane >> 4);                                     \
        LDSM4(afr[mt], sA + row * 128 + ((g ^ (row & 7)) << 4));               \
    }                                                                          \
    _Pragma("unroll")                                                          \
    for (int ng = 0; ng < 4; ng++) {                                           \
        int row = wn0 + ng * 16 + (lane & 7) + ((lane >> 4) << 3);             \
        int g   = (s16) * 2 + ((lane >> 3) & 1);                               \
        LDSM4(bfr[ng], sB + row * 128 + ((g ^ (row & 7)) << 4));               \
    }                                                                          \
    _Pragma("unroll")                                                          \
    for (int mt = 0; mt < 4; mt++)                                             \
        _Pragma("unroll")                                                      \
        for (int ni = 0; ni < 8; ni++)                                         \
            MMA(acc[mt][ni], afr[mt], bfr[ni >> 1][(ni & 1) * 2],              \
                bfr[ni >> 1][(ni & 1) * 2 + 1]);                               \
} while (0)

// ============ Kernel A: h0 = relu(Xbig @ W0big^T + b0), split -> g_h0 ============
__global__ void __launch_bounds__(256)
gemm0(const float* __restrict__ b0g)
{
    extern __shared__ __align__(128) uint8_t sm[];
    const uint32_t sb = smem_u32(sm);
    const int tid = threadIdx.x, lane = tid & 31, wid = tid >> 5;
    const int wm0 = (wid & 1) * 64, wn0 = (wid >> 1) * 64;
    const int m0 = blockIdx.x * 128, n0 = blockIdx.y * 256, c = blockIdx.z;

    float* b0s = (float*)(sm + AUX_OFF);
    for (int i = tid; i < H0n; i += 256) b0s[i] = b0g[c * H0n + i];

#define PRODUCE_A0(s, t) do {                                                  \
    _Pragma("unroll")                                                          \
    for (int i = 0; i < 4; i++) {                                              \
        int idx = tid + i * 256, row = idx >> 3, g = idx & 7;                  \
        CP16(sb + (s) * STAGE_BYTES + row * 128 + ((g ^ (row & 7)) << 4),      \
             &g_xbig[m0 + row][(t) * 64 + g * 8]);                             \
    }                                                                          \
    _Pragma("unroll")                                                          \
    for (int i = 0; i < 8; i++) {                                              \
        int idx = tid + i * 256, row = idx >> 3, g = idx & 7;                  \
        CP16(sb + (s) * STAGE_BYTES + 16384 + row * 128 + ((g ^ (row & 7)) << 4), \
             &g_w0big[c][n0 + row][(t) * 64 + g * 8]);                         \
    }                                                                          \
} while (0)

    PRODUCE_A0(0, 0); CP_COMMIT();
    PRODUCE_A0(1, 1); CP_COMMIT();

    float acc[4][8][4];
    #pragma unroll
    for (int a = 0; a < 4; a++)
        #pragma unroll
        for (int b = 0; b < 8; b++)
            #pragma unroll
            for (int r = 0; r < 4; r++) acc[a][b][r] = 0.0f;

    #pragma unroll 1
    for (int t = 0; t < 12; t++) {
        CP_WAIT1();
        __syncthreads();
        if (t + 2 < 12) { PRODUCE_A0((t + 2) % 3, t + 2); }
        CP_COMMIT();
        const uint32_t sA = sb + (t % 3) * STAGE_BYTES;
        const uint32_t sB = sA + 16384;
        #pragma unroll
        for (int s16 = 0; s16 < 4; s16++) COMPUTE_K16(s16);
    }

    // epilogue: relu(+b0), split bf16 hi/lo -> g_h0[c][m][0..511 | 512..1023]
    #pragma unroll
    for (int mt = 0; mt < 4; mt++) {
        #pragma unroll
        for (int ni = 0; ni < 8; ni++) {
            const int n = n0 + wn0 + ni * 8 + (lane & 3) * 2;
            const float bn0 = b0s[n], bn1 = b0s[n + 1];
            #pragma unroll
            for (int half = 0; half < 2; half++) {
                const int m = m0 + wm0 + mt * 16 + (lane >> 2) + half * 8;
                float v0 = fmaxf(acc[mt][ni][half * 2 + 0] + bn0, 0.0f);
                float v1 = fmaxf(acc[mt][ni][half * 2 + 1] + bn1, 0.0f);
                __nv_bfloat16 h0 = __float2bfloat16(v0), h1 = __float2bfloat16(v1);
                __nv_bfloat16 l0 = __float2bfloat16(v0 - __bfloat162float(h0));
                __nv_bfloat16 l1 = __float2bfloat16(v1 - __bfloat162float(h1));
                uint32_t hp = (uint32_t)__bfloat16_as_ushort(h0) | ((uint32_t)__bfloat16_as_ushort(h1) << 16);
                uint32_t lp = (uint32_t)__bfloat16_as_ushort(l0) | ((uint32_t)__bfloat16_as_ushort(l1) << 16);
                *(uint32_t*)&g_h0[c][m][n]       = hp;
                *(uint32_t*)&g_h0[c][m][512 + n] = lp;
            }
        }
    }
}

// ============ Kernel B: out = relu(h0 @ W1big^T + b1) . w2 + b2 ============
__global__ void __launch_bounds__(256)
gemm1(const float* __restrict__ b1g, const float* __restrict__ w2g,
      const float* __restrict__ b2g, float* __restrict__ out)
{
    extern __shared__ __align__(128) uint8_t sm[];
    const uint32_t sb = smem_u32(sm);
    const int tid = threadIdx.x, lane = tid & 31, wid = tid >> 5;
    const int wm0 = (wid & 1) * 64, wn0 = (wid >> 1) * 64;
    const int m0 = blockIdx.x * 128, c = blockIdx.y;

    float* b1s = (float*)(sm + AUX_OFF);
    float* w2s = (float*)(sm + AUX_OFF + 1024);
    float* red = (float*)(sm + AUX_OFF + 2048);     // [128][4]
    for (int i = tid; i < H1n; i += 256) { b1s[i] = b1g[c * H1n + i]; w2s[i] = w2g[c * H1n + i]; }

#define PRODUCE_A1(s, t) do {                                                  \
    _Pragma("unroll")                                                          \
    for (int i = 0; i < 4; i++) {                                              \
        int idx = tid + i * 256, row = idx >> 3, g = idx & 7;                  \
        CP16(sb + (s) * STAGE_BYTES + row * 128 + ((g ^ (row & 7)) << 4),      \
             &g_h0[c][m0 + row][((t) & 15) * 64 + g * 8]);                     \
    }                                                                          \
    _Pragma("unroll")                                                          \
    for (int i = 0; i < 8; i++) {                                              \
        int idx = tid + i * 256, row = idx >> 3, g = idx & 7;                  \
        CP16(sb + (s) * STAGE_BYTES + 16384 + row * 128 + ((g ^ (row & 7)) << 4), \
             &g_w1big[c][row][(t) * 64 + g * 8]);                              \
    }                                                                          \
} while (0)

    PRODUCE_A1(0, 0); CP_COMMIT();
    PRODUCE_A1(1, 1); CP_COMMIT();

    float acc[4][8][4];
    #pragma unroll
    for (int a = 0; a < 4; a++)
        #pragma unroll
        for (int b = 0; b < 8; b++)
            #pragma unroll
            for (int r = 0; r < 4; r++) acc[a][b][r] = 0.0f;

    #pragma unroll 1
    for (int t = 0; t < 24; t++) {
        CP_WAIT1();
        __syncthreads();
        if (t + 2 < 24) { PRODUCE_A1((t + 2) % 3, t + 2); }
        CP_COMMIT();
        const uint32_t sA = sb + (t % 3) * STAGE_BYTES;
        const uint32_t sB = sA + 16384;
        #pragma unroll
        for (int s16 = 0; s16 < 4; s16++) COMPUTE_K16(s16);
    }

    // epilogue: relu(+b1) . w2 per row, reduce quad lanes then warps
    float s[8];
    #pragma unroll
    for (int i = 0; i < 8; i++) s[i] = 0.0f;
    #pragma unroll
    for (int mt = 0; mt < 4; mt++) {
        #pragma unroll
        for (int ni = 0; ni < 8; ni++) {
            const int n = wn0 + ni * 8 + (lane & 3) * 2;
            const float bn0 = b1s[n], bn1 = b1s[n + 1];
            const float w0v = w2s[n], w1v = w2s[n + 1];
            s[mt * 2 + 0] += fmaxf(acc[mt][ni][0] + bn0, 0.0f) * w0v
                           + fmaxf(acc[mt][ni][1] + bn1, 0.0f) * w1v;
            s[mt * 2 + 1] += fmaxf(acc[mt][ni][2] + bn0, 0.0f) * w0v
                           + fmaxf(acc[mt][ni][3] + bn1, 0.0f) * w1v;
        }
    }
    #pragma unroll
    for (int i = 0; i < 8; i++) {
        s[i] += __shfl_xor_sync(0xFFFFFFFF, s[i], 1);
        s[i] += __shfl_xor_sync(0xFFFFFFFF, s[i], 2);
    }
    __syncthreads();
    if ((lane & 3) == 0) {
        #pragma unroll
        for (int mt = 0; mt < 4; mt++)
            #pragma unroll
            for (int half = 0; half < 2; half++) {
                int r = wm0 + mt * 16 + half * 8 + (lane >> 2);
                red[r * 4 + (wid >> 1)] = s[mt * 2 + half];
            }
    }
    __syncthreads();
    if (tid < 128) {
        float v = red[tid * 4] + red[tid * 4 + 1] + red[tid * 4 + 2] + red[tid * 4 + 3];
        out[(size_t)(m0 + tid) * Cn + c] = v + b2g[c];
    }
}

extern "C" void kernel_launch(void* const* d_in, const int* in_sizes, int n_in,
                              void* d_out, int out_size) {
    (void)in_sizes; (void)n_in; (void)out_size;
    const float* x  = (const float*)d_in[0];
    const float* W0 = (const float*)d_in[1];
    const float* b0 = (const float*)d_in[2];
    const float* W1 = (const float*)d_in[3];
    const float* b1 = (const float*)d_in[4];
    const float* W2 = (const float*)d_in[5];
    const float* b2 = (const float*)d_in[6];
    float* out = (float*)d_out;

    prep_x <<<2048, 256>>>(x);
    prep_w0<<<512, 256>>>(W0);
    prep_w1<<<512, 256>>>(W1);

    cudaFuncSetAttribute(gemm0, cudaFuncAttributeMaxDynamicSharedMemorySize, SMEM_TOTAL);
    cudaFuncSetAttribute(gemm1, cudaFuncAttributeMaxDynamicSharedMemorySize, SMEM_TOTAL);

    gemm0<<<dim3(128, 2, 8), 256, SMEM_TOTAL>>>(b0);
    gemm1<<<dim3(128, 8),    256, SMEM_TOTAL>>>(b1, W2, b2, out);
}

// round 5
// speedup vs baseline: 3.6727x; 1.6807x over previous
#include <cuda_runtime.h>
#include <cuda_fp16.h>
#include <cstdint>

#define Bsz 16384
#define Cn  8
#define Dd  256
#define H0n 512
#define H1n 256

// ---------------- scratch (device statics) ----------------
__device__ __align__(16) __half g_xbig[Bsz][512];          // 16MB  [x_hi | x_lo]
__device__ __align__(16) __half g_w0h [Cn][H0n][Dd];       // 2MB   w0 hi only
__device__ __align__(16) __half g_w1h [Cn][H1n][H0n];      // 2MB   w1 hi only
__device__ __align__(16) __half g_h0  [Cn][Bsz][1024];     // 268MB [h_hi | h_lo]

// ---------------- prep kernels ----------------
__device__ __forceinline__ void split8h(const float* s, uint4& hi, uint4& lo) {
    uint32_t h[4], l[4];
    #pragma unroll
    for (int i = 0; i < 4; i++) {
        float v0 = s[2*i], v1 = s[2*i+1];
        __half h0 = __float2half_rn(v0), h1 = __float2half_rn(v1);
        __half l0 = __float2half_rn(v0 - __half2float(h0));
        __half l1 = __float2half_rn(v1 - __half2float(h1));
        h[i] = (uint32_t)__half_as_ushort(h0) | ((uint32_t)__half_as_ushort(h1) << 16);
        l[i] = (uint32_t)__half_as_ushort(l0) | ((uint32_t)__half_as_ushort(l1) << 16);
    }
    hi = make_uint4(h[0], h[1], h[2], h[3]);
    lo = make_uint4(l[0], l[1], l[2], l[3]);
}
__device__ __forceinline__ uint4 cvt8h(const float* s) {
    uint32_t h[4];
    #pragma unroll
    for (int i = 0; i < 4; i++) {
        __half h0 = __float2half_rn(s[2*i]), h1 = __float2half_rn(s[2*i+1]);
        h[i] = (uint32_t)__half_as_ushort(h0) | ((uint32_t)__half_as_ushort(h1) << 16);
    }
    return make_uint4(h[0], h[1], h[2], h[3]);
}

__global__ void prep_x(const float* __restrict__ x) {
    int u = blockIdx.x * blockDim.x + threadIdx.x;   // 524288
    int k8 = u & 31, b = u >> 5;
    float buf[8];
    *(float4*)(buf)   = *(const float4*)(x + (size_t)b * Dd + k8 * 8);
    *(float4*)(buf+4) = *(const float4*)(x + (size_t)b * Dd + k8 * 8 + 4);
    uint4 hi, lo; split8h(buf, hi, lo);
    *(uint4*)&g_xbig[b][k8 * 8]       = hi;
    *(uint4*)&g_xbig[b][256 + k8 * 8] = lo;
}
__global__ void prep_w0(const float* __restrict__ W0) {
    int u = blockIdx.x * blockDim.x + threadIdx.x;   // 131072
    int k8 = u & 31, n = (u >> 5) & 511, c = u >> 14;
    float buf[8];
    const float* src = W0 + ((size_t)c * H0n + n) * Dd + k8 * 8;
    *(float4*)(buf)   = *(const float4*)(src);
    *(float4*)(buf+4) = *(const float4*)(src + 4);
    *(uint4*)&g_w0h[c][n][k8 * 8] = cvt8h(buf);
}
__global__ void prep_w1(const float* __restrict__ W1) {
    int u = blockIdx.x * blockDim.x + threadIdx.x;   // 131072
    int k8 = u & 63, n = (u >> 6) & 255, c = u >> 14;
    float buf[8];
    const float* src = W1 + ((size_t)c * H1n + n) * H0n + k8 * 8;
    *(float4*)(buf)   = *(const float4*)(src);
    *(float4*)(buf+4) = *(const float4*)(src + 4);
    *(uint4*)&g_w1h[c][n][k8 * 8] = cvt8h(buf);
}
__global__ void init_out(const float* __restrict__ b2g, float* __restrict__ out) {
    int u = blockIdx.x * blockDim.x + threadIdx.x;   // 131072
    out[u] = b2g[u & 7];
}

// ---------------- GEMM machinery ----------------
__device__ __forceinline__ uint32_t smem_u32(const void* p) {
    uint32_t a;
    asm("{ .reg .u64 t; cvta.to.shared.u64 t, %1; cvt.u32.u64 %0, t; }" : "=r"(a) : "l"(p));
    return a;
}
#define CP16(dst, src) asm volatile("cp.async.cg.shared.global [%0], [%1], 16;" :: "r"(dst), "l"(src))
#define CP_COMMIT()    asm volatile("cp.async.commit_group;" ::: "memory")
#define CP_WAIT1()     asm volatile("cp.async.wait_group 1;" ::: "memory")
#define LDSM4(r, a) \
    asm volatile("ldmatrix.sync.aligned.m8n8.x4.shared.b16 {%0,%1,%2,%3}, [%4];" \
        : "=r"((r)[0]), "=r"((r)[1]), "=r"((r)[2]), "=r"((r)[3]) : "r"(a))
#define MMA(d, a, b0, b1) \
    asm volatile("mma.sync.aligned.m16n8k16.row.col.f32.f16.f16.f32 " \
        "{%0,%1,%2,%3}, {%4,%5,%6,%7}, {%8,%9}, {%0,%1,%2,%3};" \
        : "+f"((d)[0]), "+f"((d)[1]), "+f"((d)[2]), "+f"((d)[3]) \
        : "r"((a)[0]), "r"((a)[1]), "r"((a)[2]), "r"((a)[3]), "r"(b0), "r"(b1))

// stage: A[128][64]f16 (16KB) + B[128][64]f16 (16KB) = 32KB, 3 stages
#define STAGE_BYTES 32768
#define AUX_OFF     98304
#define SMEM_TOTAL  102400

// warp tile 64x32: 4 A-ldsm, 2 B-ldsm, 16 MMA per k16
#define COMPUTE_K16(s16) do {                                                  \
    uint32_t afr[4][4], bfr[2][4];                                             \
    _Pragma("unroll")                                                          \
    for (int mt = 0; mt < 4; mt++) {                                           \
        int row = wm0 + mt * 16 + (lane & 7) + ((lane >> 3) & 1) * 8;          \
        int g   = (s16) * 2 + (lane >> 4);                                     \
        LDSM4(afr[mt], sA + row * 128 + ((g ^ (row & 7)) << 4));               \
    }                                                                          \
    _Pragma("unroll")                                                          \
    for (int ng = 0; ng < 2; ng++) {                                           \
        int row = wn0 + ng * 16 + (lane & 7) + ((lane >> 4) << 3);             \
        int g   = (s16) * 2 + ((lane >> 3) & 1);                               \
        LDSM4(bfr[ng], sB + row * 128 + ((g ^ (row & 7)) << 4));               \
    }                                                                          \
    _Pragma("unroll")                                                          \
    for (int mt = 0; mt < 4; mt++)                                             \
        _Pragma("unroll")                                                      \
        for (int ni = 0; ni < 4; ni++)                                         \
            MMA(acc[mt][ni], afr[mt], bfr[ni >> 1][(ni & 1) * 2],              \
                bfr[ni >> 1][(ni & 1) * 2 + 1]);                               \
} while (0)

// ============ Kernel A: h0 = relu(Xbig @ w0h^T + b0), fp16 split -> g_h0 ============
__global__ void __launch_bounds__(256, 2)
gemm0(const float* __restrict__ b0g)
{
    extern __shared__ __align__(128) uint8_t sm[];
    const uint32_t sb = smem_u32(sm);
    const int tid = threadIdx.x, lane = tid & 31, wid = tid >> 5;
    const int wm0 = (wid & 1) * 64, wn0 = (wid >> 1) * 32;
    const int m0 = blockIdx.x * 128, n0 = blockIdx.y * 128, c = blockIdx.z;
    const int prow = tid >> 3, pg = tid & 7;
    const uint32_t pdst = sb + prow * 128 + ((pg ^ (prow & 7)) << 4);

    float* b0s = (float*)(sm + AUX_OFF);
    for (int i = tid; i < 128; i += 256) b0s[i] = b0g[c * H0n + n0 + i];

#define PRODUCE_A0(s, t) do {                                                  \
    _Pragma("unroll")                                                          \
    for (int i = 0; i < 4; i++) {                                              \
        int row = prow + i * 32;                                               \
        uint32_t d = pdst + (s) * STAGE_BYTES + i * 4096;                      \
        CP16(d,         &g_xbig[m0 + row][(t) * 64 + pg * 8]);                 \
        CP16(d + 16384, &g_w0h[c][n0 + row][((t) & 3) * 64 + pg * 8]);         \
    }                                                                          \
} while (0)

    PRODUCE_A0(0, 0); CP_COMMIT();
    PRODUCE_A0(1, 1); CP_COMMIT();

    float acc[4][4][4];
    #pragma unroll
    for (int a = 0; a < 4; a++)
        #pragma unroll
        for (int b = 0; b < 4; b++)
            #pragma unroll
            for (int r = 0; r < 4; r++) acc[a][b][r] = 0.0f;

    #pragma unroll 1
    for (int t = 0; t < 8; t++) {
        CP_WAIT1();
        __syncthreads();
        if (t + 2 < 8) { PRODUCE_A0((t + 2) % 3, t + 2); }
        CP_COMMIT();
        const uint32_t sA = sb + (t % 3) * STAGE_BYTES;
        const uint32_t sB = sA + 16384;
        #pragma unroll
        for (int s16 = 0; s16 < 4; s16++) COMPUTE_K16(s16);
    }

    // epilogue: relu(+b0), split fp16 hi/lo -> g_h0[c][m][n | 512+n]
    #pragma unroll
    for (int mt = 0; mt < 4; mt++) {
        #pragma unroll
        for (int ni = 0; ni < 4; ni++) {
            const int nl = wn0 + ni * 8 + (lane & 3) * 2;
            const int n = n0 + nl;
            const float bn0 = b0s[nl], bn1 = b0s[nl + 1];
            #pragma unroll
            for (int half = 0; half < 2; half++) {
                const int m = m0 + wm0 + mt * 16 + (lane >> 2) + half * 8;
                float v0 = fmaxf(acc[mt][ni][half * 2 + 0] + bn0, 0.0f);
                float v1 = fmaxf(acc[mt][ni][half * 2 + 1] + bn1, 0.0f);
                __half h0 = __float2half_rn(v0), h1 = __float2half_rn(v1);
                __half l0 = __float2half_rn(v0 - __half2float(h0));
                __half l1 = __float2half_rn(v1 - __half2float(h1));
                uint32_t hp = (uint32_t)__half_as_ushort(h0) | ((uint32_t)__half_as_ushort(h1) << 16);
                uint32_t lp = (uint32_t)__half_as_ushort(l0) | ((uint32_t)__half_as_ushort(l1) << 16);
                *(uint32_t*)&g_h0[c][m][n]       = hp;
                *(uint32_t*)&g_h0[c][m][512 + n] = lp;
            }
        }
    }
}

// ============ Kernel B: out += relu(h0 @ w1h^T + b1) . w2 (partial per n-tile) ============
__global__ void __launch_bounds__(256, 2)
gemm1(const float* __restrict__ b1g, const float* __restrict__ w2g,
      float* __restrict__ out)
{
    extern __shared__ __align__(128) uint8_t sm[];
    const uint32_t sb = smem_u32(sm);
    const int tid = threadIdx.x, lane = tid & 31, wid = tid >> 5;
    const int wm0 = (wid & 1) * 64, wn0 = (wid >> 1) * 32;
    const int m0 = blockIdx.x * 128, n0 = blockIdx.y * 128, c = blockIdx.z;
    const int prow = tid >> 3, pg = tid & 7;
    const uint32_t pdst = sb + prow * 128 + ((pg ^ (prow & 7)) << 4);

    float* b1s = (float*)(sm + AUX_OFF);
    float* w2s = (float*)(sm + AUX_OFF + 512);
    float* red = (float*)(sm + AUX_OFF + 1024);     // [128][4]
    for (int i = tid; i < 128; i += 256) {
        b1s[i] = b1g[c * H1n + n0 + i];
        w2s[i] = w2g[c * H1n + n0 + i];
    }

#define PRODUCE_A1(s, t) do {                                                  \
    _Pragma("unroll")                                                          \
    for (int i = 0; i < 4; i++) {                                              \
        int row = prow + i * 32;                                               \
        uint32_t d = pdst + (s) * STAGE_BYTES + i * 4096;                      \
        CP16(d,         &g_h0[c][m0 + row][(t) * 64 + pg * 8]);                \
        CP16(d + 16384, &g_w1h[c][n0 + row][((t) & 7) * 64 + pg * 8]);         \
    }                                                                          \
} while (0)

    PRODUCE_A1(0, 0); CP_COMMIT();
    PRODUCE_A1(1, 1); CP_COMMIT();

    float acc[4][4][4];
    #pragma unroll
    for (int a = 0; a < 4; a++)
        #pragma unroll
        for (int b = 0; b < 4; b++)
            #pragma unroll
            for (int r = 0; r < 4; r++) acc[a][b][r] = 0.0f;

    #pragma unroll 1
    for (int t = 0; t < 16; t++) {
        CP_WAIT1();
        __syncthreads();
        if (t + 2 < 16) { PRODUCE_A1((t + 2) % 3, t + 2); }
        CP_COMMIT();
        const uint32_t sA = sb + (t % 3) * STAGE_BYTES;
        const uint32_t sB = sA + 16384;
        #pragma unroll
        for (int s16 = 0; s16 < 4; s16++) COMPUTE_K16(s16);
    }

    // epilogue: relu(+b1) . w2 partial dot over this CTA's 128 n's
    float s[8];
    #pragma unroll
    for (int i = 0; i < 8; i++) s[i] = 0.0f;
    #pragma unroll
    for (int mt = 0; mt < 4; mt++) {
        #pragma unroll
        for (int ni = 0; ni < 4; ni++) {
            const int nl = wn0 + ni * 8 + (lane & 3) * 2;
            const float bn0 = b1s[nl], bn1 = b1s[nl + 1];
            const float w0v = w2s[nl], w1v = w2s[nl + 1];
            s[mt * 2 + 0] += fmaxf(acc[mt][ni][0] + bn0, 0.0f) * w0v
                           + fmaxf(acc[mt][ni][1] + bn1, 0.0f) * w1v;
            s[mt * 2 + 1] += fmaxf(acc[mt][ni][2] + bn0, 0.0f) * w0v
                           + fmaxf(acc[mt][ni][3] + bn1, 0.0f) * w1v;
        }
    }
    #pragma unroll
    for (int i = 0; i < 8; i++) {
        s[i] += __shfl_xor_sync(0xFFFFFFFF, s[i], 1);
        s[i] += __shfl_xor_sync(0xFFFFFFFF, s[i], 2);
    }
    __syncthreads();
    if ((lane & 3) == 0) {
        #pragma unroll
        for (int mt = 0; mt < 4; mt++)
            #pragma unroll
            for (int half = 0; half < 2; half++) {
                int r = wm0 + mt * 16 + half * 8 + (lane >> 2);
                red[r * 4 + (wid >> 1)] = s[mt * 2 + half];
            }
    }
    __syncthreads();
    if (tid < 128) {
        float v = red[tid * 4] + red[tid * 4 + 1] + red[tid * 4 + 2] + red[tid * 4 + 3];
        atomicAdd(&out[(size_t)(m0 + tid) * Cn + c], v);
    }
}

extern "C" void kernel_launch(void* const* d_in, const int* in_sizes, int n_in,
                              void* d_out, int out_size) {
    (void)in_sizes; (void)n_in; (void)out_size;
    const float* x  = (const float*)d_in[0];
    const float* W0 = (const float*)d_in[1];
    const float* b0 = (const float*)d_in[2];
    const float* W1 = (const float*)d_in[3];
    const float* b1 = (const float*)d_in[4];
    const float* W2 = (const float*)d_in[5];
    const float* b2 = (const float*)d_in[6];
    float* out = (float*)d_out;

    prep_x  <<<2048, 256>>>(x);
    prep_w0 <<<512, 256>>>(W0);
    prep_w1 <<<512, 256>>>(W1);
    init_out<<<512, 256>>>(b2, out);

    cudaFuncSetAttribute(gemm0, cudaFuncAttributeMaxDynamicSharedMemorySize, SMEM_TOTAL);
    cudaFuncSetAttribute(gemm1, cudaFuncAttributeMaxDynamicSharedMemorySize, SMEM_TOTAL);

    gemm0<<<dim3(128, 4, 8), 256, SMEM_TOTAL>>>(b0);
    gemm1<<<dim3(128, 2, 8), 256, SMEM_TOTAL>>>(b1, W2, out);
}

// round 6
// speedup vs baseline: 5.3615x; 1.4598x over previous
#include <cuda_runtime.h>
#include <cuda_fp16.h>
#include <cstdint>

#define Bsz 16384
#define Cn  8
#define Dd  256
#define H0n 512
#define H1n 256

// ---------------- scratch (device statics) ----------------
__device__ __align__(16) __half g_xbig[Bsz][512];          // 16MB  [x_hi | x_lo]
__device__ __align__(16) __half g_w0h [Cn][H0n][Dd];       // 2MB   w0 hi only
__device__ __align__(16) __half g_w1h [Cn][H1n][H0n];      // 2MB   w1 hi only
__device__ __align__(16) __half g_h0  [Cn][Bsz][512];      // 134MB h0 fp16 (hi only)

// ---------------- prep kernels ----------------
__device__ __forceinline__ void split8h(const float* s, uint4& hi, uint4& lo) {
    uint32_t h[4], l[4];
    #pragma unroll
    for (int i = 0; i < 4; i++) {
        float v0 = s[2*i], v1 = s[2*i+1];
        __half h0 = __float2half_rn(v0), h1 = __float2half_rn(v1);
        __half l0 = __float2half_rn(v0 - __half2float(h0));
        __half l1 = __float2half_rn(v1 - __half2float(h1));
        h[i] = (uint32_t)__half_as_ushort(h0) | ((uint32_t)__half_as_ushort(h1) << 16);
        l[i] = (uint32_t)__half_as_ushort(l0) | ((uint32_t)__half_as_ushort(l1) << 16);
    }
    hi = make_uint4(h[0], h[1], h[2], h[3]);
    lo = make_uint4(l[0], l[1], l[2], l[3]);
}
__device__ __forceinline__ uint4 cvt8h(const float* s) {
    uint32_t h[4];
    #pragma unroll
    for (int i = 0; i < 4; i++) {
        __half h0 = __float2half_rn(s[2*i]), h1 = __float2half_rn(s[2*i+1]);
        h[i] = (uint32_t)__half_as_ushort(h0) | ((uint32_t)__half_as_ushort(h1) << 16);
    }
    return make_uint4(h[0], h[1], h[2], h[3]);
}

__global__ void prep_x(const float* __restrict__ x) {
    int u = blockIdx.x * blockDim.x + threadIdx.x;   // 524288
    int k8 = u & 31, b = u >> 5;
    float buf[8];
    *(float4*)(buf)   = *(const float4*)(x + (size_t)b * Dd + k8 * 8);
    *(float4*)(buf+4) = *(const float4*)(x + (size_t)b * Dd + k8 * 8 + 4);
    uint4 hi, lo; split8h(buf, hi, lo);
    *(uint4*)&g_xbig[b][k8 * 8]       = hi;
    *(uint4*)&g_xbig[b][256 + k8 * 8] = lo;
}
// one launch: w0 convert, w1 convert, out init
__global__ void prep_w(const float* __restrict__ W0, const float* __restrict__ W1,
                       const float* __restrict__ b2g, float* __restrict__ out) {
    int u = blockIdx.x * blockDim.x + threadIdx.x;   // 262144
    if (u < 131072) {
        int k8 = u & 31, n = (u >> 5) & 511, c = u >> 14;
        float buf[8];
        const float* src = W0 + ((size_t)c * H0n + n) * Dd + k8 * 8;
        *(float4*)(buf)   = *(const float4*)(src);
        *(float4*)(buf+4) = *(const float4*)(src + 4);
        *(uint4*)&g_w0h[c][n][k8 * 8] = cvt8h(buf);
    } else {
        int v = u - 131072;
        int k8 = v & 63, n = (v >> 6) & 255, c = v >> 14;
        float buf[8];
        const float* src = W1 + ((size_t)c * H1n + n) * H0n + k8 * 8;
        *(float4*)(buf)   = *(const float4*)(src);
        *(float4*)(buf+4) = *(const float4*)(src + 4);
        *(uint4*)&g_w1h[c][n][k8 * 8] = cvt8h(buf);
        out[v] = b2g[v & 7];
    }
}

// ---------------- GEMM machinery ----------------
__device__ __forceinline__ uint32_t smem_u32(const void* p) {
    uint32_t a;
    asm("{ .reg .u64 t; cvta.to.shared.u64 t, %1; cvt.u32.u64 %0, t; }" : "=r"(a) : "l"(p));
    return a;
}
#define CP16(dst, src) asm volatile("cp.async.cg.shared.global [%0], [%1], 16;" :: "r"(dst), "l"(src))
#define CP_COMMIT()    asm volatile("cp.async.commit_group;" ::: "memory")
#define CP_WAIT1()     asm volatile("cp.async.wait_group 1;" ::: "memory")
#define LDSM4(r, a) \
    asm volatile("ldmatrix.sync.aligned.m8n8.x4.shared.b16 {%0,%1,%2,%3}, [%4];" \
        : "=r"((r)[0]), "=r"((r)[1]), "=r"((r)[2]), "=r"((r)[3]) : "r"(a))
#define MMA(d, a, b0, b1) \
    asm volatile("mma.sync.aligned.m16n8k16.row.col.f32.f16.f16.f32 " \
        "{%0,%1,%2,%3}, {%4,%5,%6,%7}, {%8,%9}, {%0,%1,%2,%3};" \
        : "+f"((d)[0]), "+f"((d)[1]), "+f"((d)[2]), "+f"((d)[3]) \
        : "r"((a)[0]), "r"((a)[1]), "r"((a)[2]), "r"((a)[3]), "r"(b0), "r"(b1))

// stage: A[128][64]f16 (16KB) + B[128][64]f16 (16KB) = 32KB, 3 stages
#define STAGE_BYTES 32768
#define AUX_OFF     98304
#define SMEM_TOTAL  102400

// warp tile 64x32: 4 A-ldsm, 2 B-ldsm, 16 MMA per k16
#define COMPUTE_K16(s16) do {                                                  \
    uint32_t afr[4][4], bfr[2][4];                                             \
    _Pragma("unroll")                                                          \
    for (int mt = 0; mt < 4; mt++) {                                           \
        int row = wm0 + mt * 16 + (lane & 7) + ((lane >> 3) & 1) * 8;          \
        int g   = (s16) * 2 + (lane >> 4);                                     \
        LDSM4(afr[mt], sA + row * 128 + ((g ^ (row & 7)) << 4));               \
    }                                                                          \
    _Pragma("unroll")                                                          \
    for (int ng = 0; ng < 2; ng++) {                                           \
        int row = wn0 + ng * 16 + (lane & 7) + ((lane >> 4) << 3);             \
        int g   = (s16) * 2 + ((lane >> 3) & 1);                               \
        LDSM4(bfr[ng], sB + row * 128 + ((g ^ (row & 7)) << 4));               \
    }                                                                          \
    _Pragma("unroll")                                                          \
    for (int mt = 0; mt < 4; mt++)                                             \
        _Pragma("unroll")                                                      \
        for (int ni = 0; ni < 4; ni++)                                         \
            MMA(acc[mt][ni], afr[mt], bfr[ni >> 1][(ni & 1) * 2],              \
                bfr[ni >> 1][(ni & 1) * 2 + 1]);                               \
} while (0)

// ============ Kernel A: h0 = relu(Xbig @ w0h^T + b0) -> g_h0 (fp16) ============
__global__ void __launch_bounds__(256, 2)
gemm0(const float* __restrict__ b0g)
{
    extern __shared__ __align__(128) uint8_t sm[];
    const uint32_t sb = smem_u32(sm);
    const int tid = threadIdx.x, lane = tid & 31, wid = tid >> 5;
    const int wm0 = (wid & 1) * 64, wn0 = (wid >> 1) * 32;
    const int m0 = blockIdx.x * 128, n0 = blockIdx.y * 128, c = blockIdx.z;
    const int prow = tid >> 3, pg = tid & 7;
    const uint32_t pdst = sb + prow * 128 + ((pg ^ (prow & 7)) << 4);

    float* b0s = (float*)(sm + AUX_OFF);
    for (int i = tid; i < 128; i += 256) b0s[i] = b0g[c * H0n + n0 + i];

#define PRODUCE_A0(s, t) do {                                                  \
    _Pragma("unroll")                                                          \
    for (int i = 0; i < 4; i++) {                                              \
        int row = prow + i * 32;                                               \
        uint32_t d = pdst + (s) * STAGE_BYTES + i * 4096;                      \
        CP16(d,         &g_xbig[m0 + row][(t) * 64 + pg * 8]);                 \
        CP16(d + 16384, &g_w0h[c][n0 + row][((t) & 3) * 64 + pg * 8]);         \
    }                                                                          \
} while (0)

    PRODUCE_A0(0, 0); CP_COMMIT();
    PRODUCE_A0(1, 1); CP_COMMIT();

    float acc[4][4][4];
    #pragma unroll
    for (int a = 0; a < 4; a++)
        #pragma unroll
        for (int b = 0; b < 4; b++)
            #pragma unroll
            for (int r = 0; r < 4; r++) acc[a][b][r] = 0.0f;

    #pragma unroll 1
    for (int t = 0; t < 8; t++) {
        CP_WAIT1();
        __syncthreads();
        if (t + 2 < 8) { PRODUCE_A0((t + 2) % 3, t + 2); }
        CP_COMMIT();
        const uint32_t sA = sb + (t % 3) * STAGE_BYTES;
        const uint32_t sB = sA + 16384;
        #pragma unroll
        for (int s16 = 0; s16 < 4; s16++) COMPUTE_K16(s16);
    }

    // epilogue: relu(+b0) -> fp16 -> g_h0[c][m][n]
    #pragma unroll
    for (int mt = 0; mt < 4; mt++) {
        #pragma unroll
        for (int ni = 0; ni < 4; ni++) {
            const int nl = wn0 + ni * 8 + (lane & 3) * 2;
            const int n = n0 + nl;
            const float bn0 = b0s[nl], bn1 = b0s[nl + 1];
            #pragma unroll
            for (int half = 0; half < 2; half++) {
                const int m = m0 + wm0 + mt * 16 + (lane >> 2) + half * 8;
                float v0 = fmaxf(acc[mt][ni][half * 2 + 0] + bn0, 0.0f);
                float v1 = fmaxf(acc[mt][ni][half * 2 + 1] + bn1, 0.0f);
                __half h0 = __float2half_rn(v0), h1 = __float2half_rn(v1);
                uint32_t hp = (uint32_t)__half_as_ushort(h0) | ((uint32_t)__half_as_ushort(h1) << 16);
                *(uint32_t*)&g_h0[c][m][n] = hp;
            }
        }
    }
}

// ============ Kernel B: out += relu(h0 @ w1h^T + b1) . w2 (partial per n-tile) ============
__global__ void __launch_bounds__(256, 2)
gemm1(const float* __restrict__ b1g, const float* __restrict__ w2g,
      float* __restrict__ out)
{
    extern __shared__ __align__(128) uint8_t sm[];
    const uint32_t sb = smem_u32(sm);
    const int tid = threadIdx.x, lane = tid & 31, wid = tid >> 5;
    const int wm0 = (wid & 1) * 64, wn0 = (wid >> 1) * 32;
    const int m0 = blockIdx.x * 128, n0 = blockIdx.y * 128, c = blockIdx.z;
    const int prow = tid >> 3, pg = tid & 7;
    const uint32_t pdst = sb + prow * 128 + ((pg ^ (prow & 7)) << 4);

    float* b1s = (float*)(sm + AUX_OFF);
    float* w2s = (float*)(sm + AUX_OFF + 512);
    float* red = (float*)(sm + AUX_OFF + 1024);     // [128][4]
    for (int i = tid; i < 128; i += 256) {
        b1s[i] = b1g[c * H1n + n0 + i];
        w2s[i] = w2g[c * H1n + n0 + i];
    }

#define PRODUCE_A1(s, t) do {                                                  \
    _Pragma("unroll")                                                          \
    for (int i = 0; i < 4; i++) {                                              \
        int row = prow + i * 32;                                               \
        uint32_t d = pdst + (s) * STAGE_BYTES + i * 4096;                      \
        CP16(d,         &g_h0[c][m0 + row][(t) * 64 + pg * 8]);                \
        CP16(d + 16384, &g_w1h[c][n0 + row][((t) & 7) * 64 + pg * 8]);         \
    }                                                                          \
} while (0)

    PRODUCE_A1(0, 0); CP_COMMIT();
    PRODUCE_A1(1, 1); CP_COMMIT();

    float acc[4][4][4];
    #pragma unroll
    for (int a = 0; a < 4; a++)
        #pragma unroll
        for (int b = 0; b < 4; b++)
            #pragma unroll
            for (int r = 0; r < 4; r++) acc[a][b][r] = 0.0f;

    #pragma unroll 1
    for (int t = 0; t < 8; t++) {
        CP_WAIT1();
        __syncthreads();
        if (t + 2 < 8) { PRODUCE_A1((t + 2) % 3, t + 2); }
        CP_COMMIT();
        const uint32_t sA = sb + (t % 3) * STAGE_BYTES;
        const uint32_t sB = sA + 16384;
        #pragma unroll
        for (int s16 = 0; s16 < 4; s16++) COMPUTE_K16(s16);
    }

    // epilogue: relu(+b1) . w2 partial dot over this CTA's 128 n's
    float s[8];
    #pragma unroll
    for (int i = 0; i < 8; i++) s[i] = 0.0f;
    #pragma unroll
    for (int mt = 0; mt < 4; mt++) {
        #pragma unroll
        for (int ni = 0; ni < 4; ni++) {
            const int nl = wn0 + ni * 8 + (lane & 3) * 2;
            const float bn0 = b1s[nl], bn1 = b1s[nl + 1];
            const float w0v = w2s[nl], w1v = w2s[nl + 1];
            s[mt * 2 + 0] += fmaxf(acc[mt][ni][0] + bn0, 0.0f) * w0v
                           + fmaxf(acc[mt][ni][1] + bn1, 0.0f) * w1v;
            s[mt * 2 + 1] += fmaxf(acc[mt][ni][2] + bn0, 0.0f) * w0v
                           + fmaxf(acc[mt][ni][3] + bn1, 0.0f) * w1v;
        }
    }
    #pragma unroll
    for (int i = 0; i < 8; i++) {
        s[i] += __shfl_xor_sync(0xFFFFFFFF, s[i], 1);
        s[i] += __shfl_xor_sync(0xFFFFFFFF, s[i], 2);
    }
    __syncthreads();
    if ((lane & 3) == 0) {
        #pragma unroll
        for (int mt = 0; mt < 4; mt++)
            #pragma unroll
            for (int half = 0; half < 2; half++) {
                int r = wm0 + mt * 16 + half * 8 + (lane >> 2);
                red[r * 4 + (wid >> 1)] = s[mt * 2 + half];
            }
    }
    __syncthreads();
    if (tid < 128) {
        float v = red[tid * 4] + red[tid * 4 + 1] + red[tid * 4 + 2] + red[tid * 4 + 3];
        atomicAdd(&out[(size_t)(m0 + tid) * Cn + c], v);
    }
}

extern "C" void kernel_launch(void* const* d_in, const int* in_sizes, int n_in,
                              void* d_out, int out_size) {
    (void)in_sizes; (void)n_in; (void)out_size;
    const float* x  = (const float*)d_in[0];
    const float* W0 = (const float*)d_in[1];
    const float* b0 = (const float*)d_in[2];
    const float* W1 = (const float*)d_in[3];
    const float* b1 = (const float*)d_in[4];
    const float* W2 = (const float*)d_in[5];
    const float* b2 = (const float*)d_in[6];
    float* out = (float*)d_out;

    prep_x<<<2048, 256>>>(x);
    prep_w<<<1024, 256>>>(W0, W1, b2, out);

    cudaFuncSetAttribute(gemm0, cudaFuncAttributeMaxDynamicSharedMemorySize, SMEM_TOTAL);
    cudaFuncSetAttribute(gemm1, cudaFuncAttributeMaxDynamicSharedMemorySize, SMEM_TOTAL);

    gemm0<<<dim3(128, 4, 8), 256, SMEM_TOTAL>>>(b0);
    gemm1<<<dim3(128, 2, 8), 256, SMEM_TOTAL>>>(b1, W2, out);
}

// round 7
// speedup vs baseline: 7.3815x; 1.3768x over previous
#include <cuda_runtime.h>
#include <cuda_fp16.h>
#include <cstdint>

#define Bsz 16384
#define Cn  8
#define Dd  256
#define H0n 512
#define H1n 256

// ---------------- scratch (device statics) ----------------
__device__ __align__(16) __half g_xh  [Bsz][Dd];           // 8MB   x fp16
__device__ __align__(16) __half g_w0h [Cn][H0n][Dd];       // 2MB   w0 fp16
__device__ __align__(16) __half g_w1h [Cn][H1n][H0n];      // 2MB   w1 fp16
__device__ __align__(16) __half g_h0  [Cn][Bsz][512];      // 134MB h0 fp16

// ---------------- prep kernels ----------------
__device__ __forceinline__ uint4 cvt8h(const float* s) {
    uint32_t h[4];
    #pragma unroll
    for (int i = 0; i < 4; i++) {
        __half h0 = __float2half_rn(s[2*i]), h1 = __float2half_rn(s[2*i+1]);
        h[i] = (uint32_t)__half_as_ushort(h0) | ((uint32_t)__half_as_ushort(h1) << 16);
    }
    return make_uint4(h[0], h[1], h[2], h[3]);
}

__global__ void prep_x(const float* __restrict__ x) {
    int u = blockIdx.x * blockDim.x + threadIdx.x;   // 524288
    int k8 = u & 31, b = u >> 5;
    float buf[8];
    *(float4*)(buf)   = *(const float4*)(x + (size_t)b * Dd + k8 * 8);
    *(float4*)(buf+4) = *(const float4*)(x + (size_t)b * Dd + k8 * 8 + 4);
    *(uint4*)&g_xh[b][k8 * 8] = cvt8h(buf);
}
// one launch: w0 convert, w1 convert, out init
__global__ void prep_w(const float* __restrict__ W0, const float* __restrict__ W1,
                       const float* __restrict__ b2g, float* __restrict__ out) {
    int u = blockIdx.x * blockDim.x + threadIdx.x;   // 262144
    if (u < 131072) {
        int k8 = u & 31, n = (u >> 5) & 511, c = u >> 14;
        float buf[8];
        const float* src = W0 + ((size_t)c * H0n + n) * Dd + k8 * 8;
        *(float4*)(buf)   = *(const float4*)(src);
        *(float4*)(buf+4) = *(const float4*)(src + 4);
        *(uint4*)&g_w0h[c][n][k8 * 8] = cvt8h(buf);
    } else {
        int v = u - 131072;
        int k8 = v & 63, n = (v >> 6) & 255, c = v >> 14;
        float buf[8];
        const float* src = W1 + ((size_t)c * H1n + n) * H0n + k8 * 8;
        *(float4*)(buf)   = *(const float4*)(src);
        *(float4*)(buf+4) = *(const float4*)(src + 4);
        *(uint4*)&g_w1h[c][n][k8 * 8] = cvt8h(buf);
        out[v] = b2g[v & 7];
    }
}

// ---------------- GEMM machinery ----------------
__device__ __forceinline__ uint32_t smem_u32(const void* p) {
    uint32_t a;
    asm("{ .reg .u64 t; cvta.to.shared.u64 t, %1; cvt.u32.u64 %0, t; }" : "=r"(a) : "l"(p));
    return a;
}
#define CP16(dst, src) asm volatile("cp.async.cg.shared.global [%0], [%1], 16;" :: "r"(dst), "l"(src))
#define CP_COMMIT()    asm volatile("cp.async.commit_group;" ::: "memory")
#define CP_WAIT1()     asm volatile("cp.async.wait_group 1;" ::: "memory")
#define LDSM4(r, a) \
    asm volatile("ldmatrix.sync.aligned.m8n8.x4.shared.b16 {%0,%1,%2,%3}, [%4];" \
        : "=r"((r)[0]), "=r"((r)[1]), "=r"((r)[2]), "=r"((r)[3]) : "r"(a))
#define MMA(d, a, b0, b1) \
    asm volatile("mma.sync.aligned.m16n8k16.row.col.f32.f16.f16.f32 " \
        "{%0,%1,%2,%3}, {%4,%5,%6,%7}, {%8,%9}, {%0,%1,%2,%3};" \
        : "+f"((d)[0]), "+f"((d)[1]), "+f"((d)[2]), "+f"((d)[3]) \
        : "r"((a)[0]), "r"((a)[1]), "r"((a)[2]), "r"((a)[3]), "r"(b0), "r"(b1))

// stage: A[128][64]f16 (16KB) + B[128][64]f16 (16KB) = 32KB, 3 stages
#define STAGE_BYTES 32768
#define AUX_OFF     98304
#define SMEM_TOTAL  102400

// warp tile 64x32: 4 A-ldsm, 2 B-ldsm, 16 MMA per k16
#define COMPUTE_K16(s16) do {                                                  \
    uint32_t afr[4][4], bfr[2][4];                                             \
    _Pragma("unroll")                                                          \
    for (int mt = 0; mt < 4; mt++) {                                           \
        int row = wm0 + mt * 16 + (lane & 7) + ((lane >> 3) & 1) * 8;          \
        int g   = (s16) * 2 + (lane >> 4);                                     \
        LDSM4(afr[mt], sA + row * 128 + ((g ^ (row & 7)) << 4));               \
    }                                                                          \
    _Pragma("unroll")                                                          \
    for (int ng = 0; ng < 2; ng++) {                                           \
        int row = wn0 + ng * 16 + (lane & 7) + ((lane >> 4) << 3);             \
        int g   = (s16) * 2 + ((lane >> 3) & 1);                               \
        LDSM4(bfr[ng], sB + row * 128 + ((g ^ (row & 7)) << 4));               \
    }                                                                          \
    _Pragma("unroll")                                                          \
    for (int mt = 0; mt < 4; mt++)                                             \
        _Pragma("unroll")                                                      \
        for (int ni = 0; ni < 4; ni++)                                         \
            MMA(acc[mt][ni], afr[mt], bfr[ni >> 1][(ni & 1) * 2],              \
                bfr[ni >> 1][(ni & 1) * 2 + 1]);                               \
} while (0)

// ============ Kernel A: h0 = relu(x @ w0h^T + b0) -> g_h0 (fp16) ============
__global__ void __launch_bounds__(256, 2)
gemm0(const float* __restrict__ b0g)
{
    extern __shared__ __align__(128) uint8_t sm[];
    const uint32_t sb = smem_u32(sm);
    const int tid = threadIdx.x, lane = tid & 31, wid = tid >> 5;
    const int wm0 = (wid & 1) * 64, wn0 = (wid >> 1) * 32;
    const int m0 = blockIdx.x * 128, n0 = blockIdx.y * 128, c = blockIdx.z;
    const int prow = tid >> 3, pg = tid & 7;
    const uint32_t pdst = sb + prow * 128 + ((pg ^ (prow & 7)) << 4);

    float* b0s = (float*)(sm + AUX_OFF);
    for (int i = tid; i < 128; i += 256) b0s[i] = b0g[c * H0n + n0 + i];

#define PRODUCE_A0(s, t) do {                                                  \
    _Pragma("unroll")                                                          \
    for (int i = 0; i < 4; i++) {                                              \
        int row = prow + i * 32;                                               \
        uint32_t d = pdst + (s) * STAGE_BYTES + i * 4096;                      \
        CP16(d,         &g_xh[m0 + row][(t) * 64 + pg * 8]);                   \
        CP16(d + 16384, &g_w0h[c][n0 + row][(t) * 64 + pg * 8]);               \
    }                                                                          \
} while (0)

    PRODUCE_A0(0, 0); CP_COMMIT();
    PRODUCE_A0(1, 1); CP_COMMIT();

    float acc[4][4][4];
    #pragma unroll
    for (int a = 0; a < 4; a++)
        #pragma unroll
        for (int b = 0; b < 4; b++)
            #pragma unroll
            for (int r = 0; r < 4; r++) acc[a][b][r] = 0.0f;

    #pragma unroll 1
    for (int t = 0; t < 4; t++) {
        CP_WAIT1();
        __syncthreads();
        if (t + 2 < 4) { PRODUCE_A0((t + 2) % 3, t + 2); }
        CP_COMMIT();
        const uint32_t sA = sb + (t % 3) * STAGE_BYTES;
        const uint32_t sB = sA + 16384;
        #pragma unroll
        for (int s16 = 0; s16 < 4; s16++) COMPUTE_K16(s16);
    }

    // epilogue: relu(+b0) -> fp16 -> g_h0[c][m][n]
    #pragma unroll
    for (int mt = 0; mt < 4; mt++) {
        #pragma unroll
        for (int ni = 0; ni < 4; ni++) {
            const int nl = wn0 + ni * 8 + (lane & 3) * 2;
            const int n = n0 + nl;
            const float bn0 = b0s[nl], bn1 = b0s[nl + 1];
            #pragma unroll
            for (int half = 0; half < 2; half++) {
                const int m = m0 + wm0 + mt * 16 + (lane >> 2) + half * 8;
                float v0 = fmaxf(acc[mt][ni][half * 2 + 0] + bn0, 0.0f);
                float v1 = fmaxf(acc[mt][ni][half * 2 + 1] + bn1, 0.0f);
                __half h0 = __float2half_rn(v0), h1 = __float2half_rn(v1);
                uint32_t hp = (uint32_t)__half_as_ushort(h0) | ((uint32_t)__half_as_ushort(h1) << 16);
                *(uint32_t*)&g_h0[c][m][n] = hp;
            }
        }
    }
}

// ============ Kernel B: out += relu(h0 @ w1h^T + b1) . w2 (partial per n-tile) ============
__global__ void __launch_bounds__(256, 2)
gemm1(const float* __restrict__ b1g, const float* __restrict__ w2g,
      float* __restrict__ out)
{
    extern __shared__ __align__(128) uint8_t sm[];
    const uint32_t sb = smem_u32(sm);
    const int tid = threadIdx.x, lane = tid & 31, wid = tid >> 5;
    const int wm0 = (wid & 1) * 64, wn0 = (wid >> 1) * 32;
    const int m0 = blockIdx.x * 128, n0 = blockIdx.y * 128, c = blockIdx.z;
    const int prow = tid >> 3, pg = tid & 7;
    const uint32_t pdst = sb + prow * 128 + ((pg ^ (prow & 7)) << 4);

    float* b1s = (float*)(sm + AUX_OFF);
    float* w2s = (float*)(sm + AUX_OFF + 512);
    float* red = (float*)(sm + AUX_OFF + 1024);     // [128][4]
    for (int i = tid; i < 128; i += 256) {
        b1s[i] = b1g[c * H1n + n0 + i];
        w2s[i] = w2g[c * H1n + n0 + i];
    }

#define PRODUCE_A1(s, t) do {                                                  \
    _Pragma("unroll")                                                          \
    for (int i = 0; i < 4; i++) {                                              \
        int row = prow + i * 32;                                               \
        uint32_t d = pdst + (s) * STAGE_BYTES + i * 4096;                      \
        CP16(d,         &g_h0[c][m0 + row][(t) * 64 + pg * 8]);                \
        CP16(d + 16384, &g_w1h[c][n0 + row][((t) & 7) * 64 + pg * 8]);         \
    }                                                                          \
} while (0)

    PRODUCE_A1(0, 0); CP_COMMIT();
    PRODUCE_A1(1, 1); CP_COMMIT();

    float acc[4][4][4];
    #pragma unroll
    for (int a = 0; a < 4; a++)
        #pragma unroll
        for (int b = 0; b < 4; b++)
            #pragma unroll
            for (int r = 0; r < 4; r++) acc[a][b][r] = 0.0f;

    #pragma unroll 1
    for (int t = 0; t < 8; t++) {
        CP_WAIT1();
        __syncthreads();
        if (t + 2 < 8) { PRODUCE_A1((t + 2) % 3, t + 2); }
        CP_COMMIT();
        const uint32_t sA = sb + (t % 3) * STAGE_BYTES;
        const uint32_t sB = sA + 16384;
        #pragma unroll
        for (int s16 = 0; s16 < 4; s16++) COMPUTE_K16(s16);
    }

    // epilogue: relu(+b1) . w2 partial dot over this CTA's 128 n's
    float s[8];
    #pragma unroll
    for (int i = 0; i < 8; i++) s[i] = 0.0f;
    #pragma unroll
    for (int mt = 0; mt < 4; mt++) {
        #pragma unroll
        for (int ni = 0; ni < 4; ni++) {
            const int nl = wn0 + ni * 8 + (lane & 3) * 2;
            const float bn0 = b1s[nl], bn1 = b1s[nl + 1];
            const float w0v = w2s[nl], w1v = w2s[nl + 1];
            s[mt * 2 + 0] += fmaxf(acc[mt][ni][0] + bn0, 0.0f) * w0v
                           + fmaxf(acc[mt][ni][1] + bn1, 0.0f) * w1v;
            s[mt * 2 + 1] += fmaxf(acc[mt][ni][2] + bn0, 0.0f) * w0v
                           + fmaxf(acc[mt][ni][3] + bn1, 0.0f) * w1v;
        }
    }
    #pragma unroll
    for (int i = 0; i < 8; i++) {
        s[i] += __shfl_xor_sync(0xFFFFFFFF, s[i], 1);
        s[i] += __shfl_xor_sync(0xFFFFFFFF, s[i], 2);
    }
    __syncthreads();
    if ((lane & 3) == 0) {
        #pragma unroll
        for (int mt = 0; mt < 4; mt++)
            #pragma unroll
            for (int half = 0; half < 2; half++) {
                int r = wm0 + mt * 16 + half * 8 + (lane >> 2);
                red[r * 4 + (wid >> 1)] = s[mt * 2 + half];
            }
    }
    __syncthreads();
    if (tid < 128) {
        float v = red[tid * 4] + red[tid * 4 + 1] + red[tid * 4 + 2] + red[tid * 4 + 3];
        atomicAdd(&out[(size_t)(m0 + tid) * Cn + c], v);
    }
}

extern "C" void kernel_launch(void* const* d_in, const int* in_sizes, int n_in,
                              void* d_out, int out_size) {
    (void)in_sizes; (void)n_in; (void)out_size;
    const float* x  = (const float*)d_in[0];
    const float* W0 = (const float*)d_in[1];
    const float* b0 = (const float*)d_in[2];
    const float* W1 = (const float*)d_in[3];
    const float* b1 = (const float*)d_in[4];
    const float* W2 = (const float*)d_in[5];
    const float* b2 = (const float*)d_in[6];
    float* out = (float*)d_out;

    prep_x<<<2048, 256>>>(x);
    prep_w<<<1024, 256>>>(W0, W1, b2, out);

    cudaFuncSetAttribute(gemm0, cudaFuncAttributeMaxDynamicSharedMemorySize, SMEM_TOTAL);
    cudaFuncSetAttribute(gemm1, cudaFuncAttributeMaxDynamicSharedMemorySize, SMEM_TOTAL);

    gemm0<<<dim3(128, 4, 8), 256, SMEM_TOTAL>>>(b0);
    gemm1<<<dim3(128, 2, 8), 256, SMEM_TOTAL>>>(b1, W2, out);
}